// round 1
// baseline (speedup 1.0000x reference)
#include <cuda_runtime.h>
#include <cstdint>
#include <cstddef>

#define TOK 8192          // 4 * 2048 tokens
#define DM  2048          // d_model
#define HID 8192          // hidden

// ---------------- scratch (device globals; no allocation in kernel_launch) ----------------
__device__ float       g_s[2];                         // s1 (w_gv), s2 (w_out)
__device__ double      g_part[2][1024];                // absmean partials
__device__ signed char g_wgv_q [2u * HID * DM];        // 33.5M int8
__device__ signed char g_wout_q[(size_t)DM * HID];     // 16.7M int8
__device__ signed char g_xq    [(size_t)TOK * DM];     // quantized activations
__device__ float       g_d1[TOK];                      // absmax1/127 per token
__device__ float       g_h2   [(size_t)TOK * HID];     // SwiGLU output fp32 (256MB)
__device__ unsigned    g_amax2[TOK];                   // float-bits absmax of h2 rows
__device__ signed char g_h2q  [(size_t)TOK * HID];     // quantized h2
__device__ float       g_d2[TOK];                      // absmax2/127 per token

// ---------------- small helpers ----------------
__device__ __forceinline__ unsigned smemU32(const void* p) {
    return (unsigned)__cvta_generic_to_shared(p);
}
__device__ __forceinline__ void ldm_x4(unsigned& r0, unsigned& r1, unsigned& r2, unsigned& r3,
                                       const void* p) {
    asm volatile("ldmatrix.sync.aligned.m8n8.x4.shared.b16 {%0,%1,%2,%3}, [%4];"
                 : "=r"(r0), "=r"(r1), "=r"(r2), "=r"(r3) : "r"(smemU32(p)));
}
__device__ __forceinline__ void mma_s8(int* c, const unsigned* a, const unsigned* b) {
    asm volatile("mma.sync.aligned.m16n8k32.row.col.s32.s8.s8.s32 "
                 "{%0,%1,%2,%3}, {%4,%5,%6,%7}, {%8,%9}, {%0,%1,%2,%3};"
                 : "+r"(c[0]), "+r"(c[1]), "+r"(c[2]), "+r"(c[3])
                 : "r"(a[0]), "r"(a[1]), "r"(a[2]), "r"(a[3]), "r"(b[0]), "r"(b[1]));
}
__device__ __forceinline__ void cpa16(void* dst, const void* src) {
    asm volatile("cp.async.cg.shared.global [%0], [%1], 16;"
                 :: "r"(smemU32(dst)), "l"(src));
}
__device__ __forceinline__ signed char q8(float h, float sc) {
    float r = rintf(h * sc);                     // half-to-even, matches jnp.round
    r = fmaxf(-127.f, fminf(127.f, r));
    return (signed char)r;
}

// ---------------- 1) abs-mean partial reduction (deterministic) ----------------
__global__ void k_absmean(const float4* __restrict__ wgv, const float4* __restrict__ wout) {
    int sel = blockIdx.x >= 1024;
    const float4* p = sel ? wout : wgv;
    int n4 = sel ? (DM * HID / 4) : (2 * HID * DM / 4);
    int b = blockIdx.x & 1023;
    float acc = 0.f;
    for (int i = b * 256 + threadIdx.x; i < n4; i += 1024 * 256) {
        float4 v = p[i];
        acc += fabsf(v.x) + fabsf(v.y) + fabsf(v.z) + fabsf(v.w);
    }
    __shared__ float sm[8];
    for (int o = 16; o; o >>= 1) acc += __shfl_xor_sync(~0u, acc, o);
    if ((threadIdx.x & 31) == 0) sm[threadIdx.x >> 5] = acc;
    __syncthreads();
    if (threadIdx.x == 0) {
        float t = 0.f;
        #pragma unroll
        for (int i = 0; i < 8; i++) t += sm[i];
        g_part[sel][b] = (double)t;
    }
}

// ---------------- 2) finalize scales + zero absmax2 ----------------
__global__ void k_final() {
    __shared__ double sm[32];
    int t = threadIdx.x; // 1024 threads
    for (int sel = 0; sel < 2; ++sel) {
        double a = g_part[sel][t];
        for (int o = 16; o; o >>= 1) a += __shfl_xor_sync(~0u, a, o);
        if ((t & 31) == 0) sm[t >> 5] = a;
        __syncthreads();
        if (t == 0) {
            double s = 0.0;
            #pragma unroll
            for (int i = 0; i < 32; i++) s += sm[i];
            double n = sel ? (double)DM * HID : (double)2 * HID * DM;
            g_s[sel] = fmaxf((float)(s / n), 1e-5f);
        }
        __syncthreads();
    }
    for (int i = t; i < TOK; i += 1024) g_amax2[i] = 0u;
}

// ---------------- 3) ternary weight quantization ----------------
__global__ void k_wquant(const float4* __restrict__ w, int n4, int sel) {
    float inv = 1.0f / g_s[sel];
    char4* q = sel ? (char4*)g_wout_q : (char4*)g_wgv_q;
    for (int i = blockIdx.x * blockDim.x + threadIdx.x; i < n4; i += gridDim.x * blockDim.x) {
        float4 v = w[i];
        char4 c;
        c.x = (signed char)fmaxf(-1.f, fminf(1.f, rintf(v.x * inv)));
        c.y = (signed char)fmaxf(-1.f, fminf(1.f, rintf(v.y * inv)));
        c.z = (signed char)fmaxf(-1.f, fminf(1.f, rintf(v.z * inv)));
        c.w = (signed char)fmaxf(-1.f, fminf(1.f, rintf(v.w * inv)));
        q[i] = c;
    }
}

// ---------------- 4) RMSNorm + per-token act quant ----------------
__global__ void k_rmsquant(const float4* __restrict__ x, const float4* __restrict__ nw) {
    int row = blockIdx.x, t = threadIdx.x;
    int lane = t & 31, warp = t >> 5;
    const float4* xr = x + (size_t)row * (DM / 4);
    float4 v0 = xr[t], v1 = xr[t + 256];
    float ss = v0.x * v0.x + v0.y * v0.y + v0.z * v0.z + v0.w * v0.w
             + v1.x * v1.x + v1.y * v1.y + v1.z * v1.z + v1.w * v1.w;

    __shared__ float red[8];
    __shared__ float bval;
    for (int o = 16; o; o >>= 1) ss += __shfl_xor_sync(~0u, ss, o);
    if (lane == 0) red[warp] = ss;
    __syncthreads();
    if (t == 0) {
        float s = 0.f;
        #pragma unroll
        for (int i = 0; i < 8; i++) s += red[i];
        bval = s;
    }
    __syncthreads();
    float rstd = rsqrtf(bval * (1.f / DM) + 1e-5f);

    float4 w0 = nw[t], w1 = nw[t + 256];
    float h[8] = { v0.x * rstd * w0.x, v0.y * rstd * w0.y, v0.z * rstd * w0.z, v0.w * rstd * w0.w,
                   v1.x * rstd * w1.x, v1.y * rstd * w1.y, v1.z * rstd * w1.z, v1.w * rstd * w1.w };
    float am = 0.f;
    #pragma unroll
    for (int i = 0; i < 8; i++) am = fmaxf(am, fabsf(h[i]));
    __syncthreads();
    for (int o = 16; o; o >>= 1) am = fmaxf(am, __shfl_xor_sync(~0u, am, o));
    if (lane == 0) red[warp] = am;
    __syncthreads();
    if (t == 0) {
        float m = 0.f;
        #pragma unroll
        for (int i = 0; i < 8; i++) m = fmaxf(m, red[i]);
        m = fmaxf(m, 1e-5f);
        bval = m;
        g_d1[row] = m * (1.f / 127.f);
    }
    __syncthreads();
    float sc = 127.f / bval;

    char4 c0, c1;
    c0.x = q8(h[0], sc); c0.y = q8(h[1], sc); c0.z = q8(h[2], sc); c0.w = q8(h[3], sc);
    c1.x = q8(h[4], sc); c1.y = q8(h[5], sc); c1.z = q8(h[6], sc); c1.w = q8(h[7], sc);
    char4* dst = (char4*)(g_xq + (size_t)row * DM);
    dst[t] = c0;
    dst[t + 256] = c1;
}

// ---------------- 5/7) int8 GEMM core (mma.sync m16n8k32 s8) ----------------
// Block tile: 128(M) x 64(N) x 64(K), NSETS B-tiles (value+gate for phase 1).
// 8 warps = 4(M) x 2(N); warp tile 32x32 per set.
template <int PHASE>
__global__ __launch_bounds__(256, 2) void k_gemm(const float* __restrict__ resid,
                                                 float* __restrict__ dout) {
    constexpr int NSETS = (PHASE == 1) ? 2 : 1;
    constexpr int K = (PHASE == 1) ? DM : HID;
    constexpr int NK = K / 64;
    const signed char* A = (PHASE == 1) ? g_xq : g_h2q;
    const signed char* B = (PHASE == 1) ? g_wgv_q : g_wout_q;
    const float* dA = (PHASE == 1) ? g_d1 : g_d2;

    __shared__ signed char As[2][128 * 80];           // stride 80B: conflict-free ldmatrix
    __shared__ signed char Bs[2][NSETS][64 * 80];
    __shared__ unsigned samax[128];

    int tid = threadIdx.x;
    int mBase = blockIdx.y * 128;
    int nBase = blockIdx.x * 64;

    if (PHASE == 1)
        for (int i = tid; i < 128; i += 256) samax[i] = 0u;

    auto load = [&](int kt, int st) {
        int k0 = kt * 64;
        #pragma unroll
        for (int p = 0; p < 2; p++) {
            int c = tid + p * 256;
            int r = c >> 2, ch = c & 3;
            cpa16(&As[st][r * 80 + ch * 16], A + (size_t)(mBase + r) * K + k0 + ch * 16);
        }
        #pragma unroll
        for (int s = 0; s < NSETS; s++) {
            int r = tid >> 2, ch = tid & 3;
            cpa16(&Bs[st][s][r * 80 + ch * 16],
                  B + (size_t)(nBase + s * HID + r) * K + k0 + ch * 16);
        }
    };

    int lane = tid & 31, warp = tid >> 5;
    int wm = warp & 3, wn = warp >> 2;
    int acc[NSETS][2][4][4];
    #pragma unroll
    for (int s = 0; s < NSETS; s++)
        #pragma unroll
        for (int mt = 0; mt < 2; mt++)
            #pragma unroll
            for (int nt = 0; nt < 4; nt++)
                #pragma unroll
                for (int r = 0; r < 4; r++) acc[s][mt][nt][r] = 0;

    load(0, 0); asm volatile("cp.async.commit_group;");
    load(1, 1); asm volatile("cp.async.commit_group;");

    #pragma unroll 1
    for (int it = 0; it < NK; ++it) {
        asm volatile("cp.async.wait_group 1;");
        __syncthreads();
        int st = it & 1;
        #pragma unroll
        for (int kk = 0; kk < 2; ++kk) {
            unsigned a[2][4];
            int sub = lane >> 3;
            #pragma unroll
            for (int mt = 0; mt < 2; ++mt) {
                int r = wm * 32 + mt * 16 + (sub & 1) * 8 + (lane & 7);
                int cb = kk * 32 + (sub >> 1) * 16;
                ldm_x4(a[mt][0], a[mt][1], a[mt][2], a[mt][3], &As[st][r * 80 + cb]);
            }
            unsigned b[NSETS][4][2];
            #pragma unroll
            for (int s = 0; s < NSETS; s++)
                #pragma unroll
                for (int ntp = 0; ntp < 2; ntp++) {
                    int r = wn * 32 + ntp * 16 + (sub >> 1) * 8 + (lane & 7);
                    int cb = kk * 32 + (sub & 1) * 16;
                    unsigned r0, r1, r2, r3;
                    ldm_x4(r0, r1, r2, r3, &Bs[st][s][r * 80 + cb]);
                    b[s][ntp * 2][0] = r0; b[s][ntp * 2][1] = r1;
                    b[s][ntp * 2 + 1][0] = r2; b[s][ntp * 2 + 1][1] = r3;
                }
            #pragma unroll
            for (int s = 0; s < NSETS; s++)
                #pragma unroll
                for (int mt = 0; mt < 2; mt++)
                    #pragma unroll
                    for (int nt = 0; nt < 4; nt++)
                        mma_s8(acc[s][mt][nt], a[mt], b[s][nt]);
        }
        __syncthreads();
        if (it + 2 < NK) load(it + 2, st);
        asm volatile("cp.async.commit_group;");
    }

    // ---------------- epilogue ----------------
    float s = g_s[PHASE - 1];
    #pragma unroll
    for (int mt = 0; mt < 2; ++mt) {
        #pragma unroll
        for (int rh = 0; rh < 2; ++rh) {
            int rloc = wm * 32 + mt * 16 + rh * 8 + (lane >> 2);
            int grow = mBase + rloc;
            float d = dA[grow] * s;
            if (PHASE == 1) {
                float rmax = 0.f;
                #pragma unroll
                for (int nt = 0; nt < 4; nt++) {
                    float v0 = acc[0][mt][nt][rh * 2] * d;
                    float v1 = acc[0][mt][nt][rh * 2 + 1] * d;
                    float gg0 = acc[1][mt][nt][rh * 2] * d;
                    float gg1 = acc[1][mt][nt][rh * 2 + 1] * d;
                    float h0 = v0 * (gg0 / (1.f + expf(-gg0)));   // value * silu(gate)
                    float h1 = v1 * (gg1 / (1.f + expf(-gg1)));
                    rmax = fmaxf(rmax, fmaxf(fabsf(h0), fabsf(h1)));
                    int gc = nBase + wn * 32 + nt * 8 + (lane & 3) * 2;
                    *(float2*)(g_h2 + (size_t)grow * HID + gc) = make_float2(h0, h1);
                }
                atomicMax(&samax[rloc], __float_as_uint(rmax));
            } else {
                #pragma unroll
                for (int nt = 0; nt < 4; nt++) {
                    int gc = nBase + wn * 32 + nt * 8 + (lane & 3) * 2;
                    float2 rr = *(const float2*)(resid + (size_t)grow * DM + gc);
                    float2 o = make_float2(rr.x + acc[0][mt][nt][rh * 2] * d,
                                           rr.y + acc[0][mt][nt][rh * 2 + 1] * d);
                    *(float2*)(dout + (size_t)grow * DM + gc) = o;
                }
            }
        }
    }
    if (PHASE == 1) {
        __syncthreads();
        for (int i = tid; i < 128; i += 256)
            atomicMax(&g_amax2[mBase + i], samax[i]);
    }
}

// ---------------- 6) quantize h2 ----------------
__global__ void k_h2quant() {
    int row = blockIdx.y;
    float am = fmaxf(__uint_as_float(g_amax2[row]), 1e-5f);
    float sc = 127.f / am;
    int i = blockIdx.x * 256 + threadIdx.x;          // 2048 float4 per row, grid.x = 8
    float4 v = ((const float4*)(g_h2 + (size_t)row * HID))[i];
    char4 c;
    c.x = q8(v.x, sc); c.y = q8(v.y, sc); c.z = q8(v.z, sc); c.w = q8(v.w, sc);
    ((char4*)(g_h2q + (size_t)row * HID))[i] = c;
    if (i == 0) g_d2[row] = am * (1.f / 127.f);
}

// ---------------- launcher ----------------
extern "C" void kernel_launch(void* const* d_in, const int* in_sizes, int n_in,
                              void* d_out, int out_size) {
    const float* x    = (const float*)d_in[0];   // [4,2048,2048]
    const float* nw   = (const float*)d_in[1];   // [2048]
    const float* wgv  = (const float*)d_in[2];   // [16384,2048]
    const float* wout = (const float*)d_in[3];   // [2048,8192]
    float* out = (float*)d_out;

    k_absmean<<<2048, 256>>>((const float4*)wgv, (const float4*)wout);
    k_final<<<1, 1024>>>();
    k_wquant<<<4096, 256>>>((const float4*)wgv, 2 * HID * DM / 4, 0);
    k_wquant<<<2048, 256>>>((const float4*)wout, DM * HID / 4, 1);
    k_rmsquant<<<TOK, 256>>>((const float4*)x, (const float4*)nw);
    k_gemm<1><<<dim3(HID / 64, TOK / 128), 256>>>(nullptr, nullptr);
    k_h2quant<<<dim3(8, TOK), 256>>>();
    k_gemm<2><<<dim3(DM / 64, TOK / 128), 256>>>(x, out);
}